// round 11
// baseline (speedup 1.0000x reference)
#include <cuda_runtime.h>
#include <cuda_fp16.h>
#include <mma.h>
#include <cstdint>

using namespace nvcuda;

// Problem constants (fixed by the reference)
#define B_ 4
#define S_ 2048
#define E_ 1024
#define H_ 16
#define D_ 64
#define M_ (B_*S_)   // 8192 rows

// Scratch (device globals: allocation-free rule)
__device__ __half g_Qh[M_*E_];
__device__ __half g_Kh[M_*E_];
__device__ __half g_Vh[M_*E_];
__device__ __half g_Oh[M_*E_];
__device__ __half g_Xq[M_*E_];
__device__ __half g_Xk[M_*E_];
__device__ __half g_Xv[M_*E_];
__device__ __half g_Wq[E_*E_];
__device__ __half g_Wk[E_*E_];
__device__ __half g_Wv[E_*E_];
__device__ __half g_Wo[E_*E_];

// ---------------------------------------------------------------------------
// One-launch fp32->fp16 convert of all 7 tensors.
// Blocks 0..24575: inputs (3 x 8192 blocks). 24576..28671: weights (4 x 1024).
// ---------------------------------------------------------------------------
struct ConvArgs {
  const float* src[7];
  __half* dst[7];
};
__global__ void conv_all(ConvArgs a) {
  int bid = blockIdx.x;
  int z, off;
  if (bid < 24576) { z = bid >> 13;            off = bid & 8191; }
  else             { z = 3 + ((bid - 24576) >> 10); off = (bid - 24576) & 1023; }
  int i = off * 256 + threadIdx.x;
  float4 v = ((const float4*)a.src[z])[i];
  __half2 h0 = __floats2half2_rn(v.x, v.y);
  __half2 h1 = __floats2half2_rn(v.z, v.w);
  uint2 u; u.x = *(uint32_t*)&h0; u.y = *(uint32_t*)&h1;
  ((uint2*)a.dst[z])[i] = u;
}

// ---------------------------------------------------------------------------
__device__ __forceinline__ uint32_t smem_u32(const void* p) {
  uint32_t a;
  asm("{ .reg .u64 t; cvta.to.shared.u64 t, %1; cvt.u32.u64 %0, t; }" : "=r"(a) : "l"(p));
  return a;
}
__device__ __forceinline__ void cp16(uint32_t dst, const void* src) {
  asm volatile("cp.async.cg.shared.global [%0], [%1], 16;" :: "r"(dst), "l"(src));
}
#define CP_COMMIT() asm volatile("cp.async.commit_group;" ::: "memory")
#define CP_WAIT0()  asm volatile("cp.async.wait_group 0;" ::: "memory")
#define CP_WAIT1()  asm volatile("cp.async.wait_group 1;" ::: "memory")

// ---------------------------------------------------------------------------
// GEMM: block tile 256x128, BK=64, 512 threads (16 warps, 4/SMSP),
// warp tile 32x64, 3-stage cp.async pipeline (wait_group 1 steady state).
// ---------------------------------------------------------------------------
#define BM 256
#define BN 128
#define BK 64
#define LDH 72                          // 64 + 8 pad halves (row 144B)
#define A_STG (BM*LDH)                  // 18432 halves
#define B_STG (BN*LDH)                  // 9216 halves
#define STG_TOT (A_STG + B_STG)         // 27648 halves = 55296 B
#define NSTAGE 3
#define GEMM_SMEM (NSTAGE*STG_TOT*2)    // 165888 bytes

#define ROPE_C (13.287712379549449f / 32.0f)   // log2(10000)/32
#define QSCALE 0.18033688011112042f            // (1/8)*log2(e)

__device__ __forceinline__ void gemm_mainloop(
    const __half* __restrict__ A, const __half* __restrict__ W,
    __half* sh, int m0, int n0,
    wmma::fragment<wmma::accumulator, 16, 16, 16, float> (&acc)[2][4]) {
  const int tid = threadIdx.x;
  const int wid = tid >> 5;
  const int wm = wid & 7;       // 8 row bands x 32
  const int wn = wid >> 3;      // 2 col bands x 64
  const uint32_t sb = smem_u32(sh);
  const int K = E_;

  auto stage = [&](int kt) {
    const int s = kt % NSTAGE;
    const uint32_t sbase = sb + (uint32_t)(s * STG_TOT) * 2;
    const __half* Ab = A + (size_t)m0 * K + kt * BK;
    const __half* Wb = W + (size_t)n0 * K + kt * BK;
    #pragma unroll
    for (int it = 0; it < 4; it++) {                 // A: 256 rows x 64
      int idx = it * 512 + tid;
      int r = idx >> 3, c = (idx & 7) * 8;
      cp16(sbase + (uint32_t)(r*LDH + c) * 2, Ab + (size_t)r * K + c);
    }
    #pragma unroll
    for (int it = 0; it < 2; it++) {                 // B: 128 rows x 64
      int idx = it * 512 + tid;
      int r = idx >> 3, c = (idx & 7) * 8;
      cp16(sbase + (uint32_t)(A_STG + r*LDH + c) * 2, Wb + (size_t)r * K + c);
    }
    CP_COMMIT();
  };

  #pragma unroll
  for (int i = 0; i < 2; i++)
    #pragma unroll
    for (int j = 0; j < 4; j++) wmma::fill_fragment(acc[i][j], 0.0f);

  const int ntile = K / BK;    // 16
  stage(0); stage(1);
  for (int t = 0; t < ntile; t++) {
    if (t < ntile - 1) { CP_WAIT1(); } else { CP_WAIT0(); }
    __syncthreads();
    if (t + 2 < ntile) stage(t + 2);
    const __half (*As)[LDH] = (const __half(*)[LDH])(sh + (t % NSTAGE)*STG_TOT);
    const __half (*Bs)[LDH] = (const __half(*)[LDH])(sh + (t % NSTAGE)*STG_TOT + A_STG);
    #pragma unroll
    for (int ks = 0; ks < BK; ks += 16) {
      wmma::fragment<wmma::matrix_a, 16, 16, 16, __half, wmma::row_major> af[2];
      wmma::fragment<wmma::matrix_b, 16, 16, 16, __half, wmma::col_major> bf[4];
      #pragma unroll
      for (int i = 0; i < 2; i++)
        wmma::load_matrix_sync(af[i], &As[wm*32 + i*16][ks], LDH);
      #pragma unroll
      for (int j = 0; j < 4; j++)
        wmma::load_matrix_sync(bf[j], &Bs[wn*64 + j*16][ks], LDH);
      #pragma unroll
      for (int i = 0; i < 2; i++)
        #pragma unroll
        for (int j = 0; j < 4; j++)
          wmma::mma_sync(acc[i][j], af[i], bf[j], acc[i][j]);
    }
  }
}

// ---------------------------------------------------------------------------
// Fused QKV projection; mode: 0=Q (RoPE+scale), 1=K (RoPE), 2=V.
// Epilogue: two passes of 128 rows staged through smem (64KB each).
// ---------------------------------------------------------------------------
__global__ __launch_bounds__(512)
void gemm_qkv(const __half* __restrict__ Xq, const __half* __restrict__ Xk,
              const __half* __restrict__ Xv,
              const __half* __restrict__ Wq, const __half* __restrict__ Wk,
              const __half* __restrict__ Wv,
              __half* __restrict__ Qo, __half* __restrict__ Ko,
              __half* __restrict__ Vo) {
  extern __shared__ __half sh[];
  const int mode = blockIdx.z;
  const __half* A = (mode == 0) ? Xq : (mode == 1) ? Xk : Xv;
  const __half* W = (mode == 0) ? Wq : (mode == 1) ? Wk : Wv;
  __half* C       = (mode == 0) ? Qo : (mode == 1) ? Ko : Vo;
  const int m0 = blockIdx.y * BM, n0 = blockIdx.x * BN;
  const int tid = threadIdx.x;
  const int wid = tid >> 5, wm = wid & 7, wn = wid >> 3;

  wmma::fragment<wmma::accumulator, 16, 16, 16, float> acc[2][4];
  gemm_mainloop(A, W, sh, m0, n0, acc);

  float (*Cs)[BN] = (float(*)[BN])sh;     // 128x128 f32 = 64KB per pass
  const int r  = tid >> 2;                // 0..127
  const int c0 = (tid & 3) * 32;          // 0,32,64,96

  #pragma unroll
  for (int p = 0; p < 2; p++) {
    __syncthreads();                      // previous pass reads done
    if ((wm >> 2) == p) {
      #pragma unroll
      for (int i = 0; i < 2; i++)
        #pragma unroll
        for (int j = 0; j < 4; j++)
          wmma::store_matrix_sync(&Cs[(wm & 3)*32 + i*16][wn*64 + j*16], acc[i][j],
                                  BN, wmma::mem_row_major);
    }
    __syncthreads();

    const int grow = m0 + p*128 + r;
    __half* dst = C + (size_t)grow * E_ + n0 + c0;
    float ov[32];
    if (mode < 2) {
      const float scale = (mode == 0) ? QSCALE : 1.0f;
      const int spos = grow & (S_ - 1);
      const bool first = (c0 & 32) == 0;   // x1-half vs x2-half of the head
      #pragma unroll
      for (int j = 0; j < 32; j++) {
        float inv = exp2f(-(float)j * ROPE_C);
        float ang = (float)spos * inv;
        float sv, cv;
        sincosf(ang, &sv, &cv);
        if (first) {
          float x1 = Cs[r][c0 + j], x2 = Cs[r][c0 + j + 32];
          ov[j] = (x1*cv - x2*sv) * scale;
        } else {
          float x2 = Cs[r][c0 + j], x1 = Cs[r][c0 + j - 32];
          ov[j] = (x2*cv + x1*sv) * scale;
        }
      }
    } else {
      #pragma unroll
      for (int j = 0; j < 32; j++) ov[j] = Cs[r][c0 + j];
    }
    uint32_t pk[16];
    #pragma unroll
    for (int j = 0; j < 16; j++) {
      __half2 h2 = __floats2half2_rn(ov[2*j], ov[2*j+1]);
      pk[j] = *(uint32_t*)&h2;
    }
    #pragma unroll
    for (int q = 0; q < 4; q++)
      *(uint4*)(dst + q*8) = *(uint4*)&pk[q*4];
  }
}

// ---------------------------------------------------------------------------
// Output projection: fp16 in, fp32 out (direct wmma stores).
// ---------------------------------------------------------------------------
__global__ __launch_bounds__(512)
void gemm_out(const __half* __restrict__ A, const __half* __restrict__ W,
              float* __restrict__ C) {
  extern __shared__ __half sh[];
  const int m0 = blockIdx.y * BM, n0 = blockIdx.x * BN;
  const int tid = threadIdx.x;
  const int wid = tid >> 5, wm = wid & 7, wn = wid >> 3;

  wmma::fragment<wmma::accumulator, 16, 16, 16, float> acc[2][4];
  gemm_mainloop(A, W, sh, m0, n0, acc);

  #pragma unroll
  for (int i = 0; i < 2; i++)
    #pragma unroll
    for (int j = 0; j < 4; j++)
      wmma::store_matrix_sync(&C[(size_t)(m0 + wm*32 + i*16) * E_ + n0 + wn*64 + j*16],
                              acc[i][j], E_, wmma::mem_row_major);
}

// ---------------------------------------------------------------------------
// Causal flash attention, 128-row query tiles (unchanged from best config).
// ---------------------------------------------------------------------------
#define LA 72
#define ATT_SMEM (36864 + 18432 + 18432 + 18432 + 18432)   // 110592

__global__ __launch_bounds__(256)
void attn_f16(const __half* __restrict__ Q, const __half* __restrict__ K,
              const __half* __restrict__ V, __half* __restrict__ O) {
  extern __shared__ char smraw[];
  float  (*Ss)[LA]     = (float(*)[LA])(smraw);
  __half (*Qh)[LA]     = (__half(*)[LA])(smraw + 36864);
  __half (*Kh)[64][LA] = (__half(*)[64][LA])(smraw + 55296);
  __half (*Vh)[64][LA] = (__half(*)[64][LA])(smraw + 73728);
  __half (*Ph)[LA]     = (__half(*)[LA])(smraw + 92160);

  const int tid = threadIdx.x;
  const int wid = tid >> 5;
  const int b = blockIdx.y >> 4, h = blockIdx.y & 15;
  const int q0 = blockIdx.x * 128;

  const size_t gbase = (size_t)(b*S_)*E_ + h*64;
  const uint32_t kb0 = smem_u32(&Kh[0][0][0]);
  const uint32_t vb0 = smem_u32(&Vh[0][0][0]);

  auto prefetch = [&](int t) {
    int s = t & 1;
    #pragma unroll
    for (int it = 0; it < 2; it++) {
      int idx = it*256 + tid;
      int r = idx >> 3, c = (idx & 7) * 8;
      const __half* ks = K + gbase + (size_t)(t*64 + r)*E_ + c;
      const __half* vs = V + gbase + (size_t)(t*64 + r)*E_ + c;
      cp16(kb0 + (uint32_t)(s*64*LA + r*LA + c) * 2, ks);
      cp16(vb0 + (uint32_t)(s*64*LA + r*LA + c) * 2, vs);
    }
    CP_COMMIT();
  };

  {
    #pragma unroll
    for (int it = 0; it < 4; it++) {
      int idx = it*256 + tid;
      int r = idx >> 3, c = (idx & 7) * 8;
      *(uint4*)&Qh[r][c] = *(const uint4*)(Q + gbase + (size_t)(q0 + r)*E_ + c);
    }
  }

  const int row = tid >> 1;
  const int c0  = (tid & 1) * 32;

  float o[32];
  #pragma unroll
  for (int j = 0; j < 32; j++) o[j] = 0.f;
  float m_i = -1e30f, l_i = 0.f;

  const int nt = q0/64 + 2;
  prefetch(0);
  for (int t = 0; t < nt; t++) {
    const int k0 = t*64;
    const int s = t & 1;
    CP_WAIT0();
    __syncthreads();
    if (t + 1 < nt) prefetch(t + 1);

    { // S = Q K^T
      wmma::fragment<wmma::accumulator, 16, 16, 16, float> sa[4];
      #pragma unroll
      for (int j = 0; j < 4; j++) wmma::fill_fragment(sa[j], 0.0f);
      #pragma unroll
      for (int ks_ = 0; ks_ < 64; ks_ += 16) {
        wmma::fragment<wmma::matrix_a, 16, 16, 16, __half, wmma::row_major> af;
        wmma::load_matrix_sync(af, &Qh[wid*16][ks_], LA);
        #pragma unroll
        for (int j = 0; j < 4; j++) {
          wmma::fragment<wmma::matrix_b, 16, 16, 16, __half, wmma::col_major> bf;
          wmma::load_matrix_sync(bf, &Kh[s][j*16][ks_], LA);
          wmma::mma_sync(sa[j], af, bf, sa[j]);
        }
      }
      #pragma unroll
      for (int j = 0; j < 4; j++)
        wmma::store_matrix_sync(&Ss[wid*16][j*16], sa[j], LA, wmma::mem_row_major);
    }
    __syncthreads();

    float corr;
    {
      float sv[32];
      #pragma unroll
      for (int j = 0; j < 32; j++) {
        float sc = Ss[row][c0+j];
        sv[j] = (k0 + c0 + j > q0 + row) ? -1e30f : sc;
      }
      float rm = sv[0];
      #pragma unroll
      for (int j = 1; j < 32; j++) rm = fmaxf(rm, sv[j]);
      rm = fmaxf(rm, __shfl_xor_sync(0xffffffffu, rm, 1));
      float mn = fmaxf(m_i, rm);
      corr = exp2f(m_i - mn);
      m_i = mn;
      float rs = 0.f;
      #pragma unroll
      for (int j = 0; j < 32; j += 2) {
        float p0 = exp2f(sv[j]   - mn);
        float p1 = exp2f(sv[j+1] - mn);
        rs += p0 + p1;
        *(half2*)&Ph[row][c0+j] = __floats2half2_rn(p0, p1);
      }
      rs += __shfl_xor_sync(0xffffffffu, rs, 1);
      l_i = l_i*corr + rs;
    }
    __syncthreads();

    { // O_part = P V
      wmma::fragment<wmma::accumulator, 16, 16, 16, float> oa[4];
      #pragma unroll
      for (int j = 0; j < 4; j++) wmma::fill_fragment(oa[j], 0.0f);
      #pragma unroll
      for (int ks_ = 0; ks_ < 64; ks_ += 16) {
        wmma::fragment<wmma::matrix_a, 16, 16, 16, __half, wmma::row_major> af;
        wmma::load_matrix_sync(af, &Ph[wid*16][ks_], LA);
        #pragma unroll
        for (int j = 0; j < 4; j++) {
          wmma::fragment<wmma::matrix_b, 16, 16, 16, __half, wmma::row_major> bf;
          wmma::load_matrix_sync(bf, &Vh[s][ks_][j*16], LA);
          wmma::mma_sync(oa[j], af, bf, oa[j]);
        }
      }
      #pragma unroll
      for (int j = 0; j < 4; j++)
        wmma::store_matrix_sync(&Ss[wid*16][j*16], oa[j], LA, wmma::mem_row_major);
    }
    __syncthreads();

    #pragma unroll
    for (int j = 0; j < 32; j++)
      o[j] = o[j]*corr + Ss[row][c0+j];
  }

  {
    float inv = 1.0f / l_i;
    __half* dst = O + gbase + (size_t)(q0 + row)*E_ + c0;
    uint32_t pk[16];
    #pragma unroll
    for (int j = 0; j < 16; j++) {
      __half2 h2 = __floats2half2_rn(o[2*j]*inv, o[2*j+1]*inv);
      pk[j] = *(uint32_t*)&h2;
    }
    #pragma unroll
    for (int q = 0; q < 4; q++)
      *(uint4*)(dst + q*8) = *(uint4*)&pk[q*4];
  }
}

// ---------------------------------------------------------------------------
extern "C" void kernel_launch(void* const* d_in, const int* in_sizes, int n_in,
                              void* d_out, int out_size) {
  (void)in_sizes; (void)n_in; (void)out_size;
  const float* query = (const float*)d_in[0];
  const float* key   = (const float*)d_in[1];
  const float* value = (const float*)d_in[2];
  const float* Wq    = (const float*)d_in[3];
  const float* Wk    = (const float*)d_in[4];
  const float* Wv    = (const float*)d_in[5];
  const float* Wo    = (const float*)d_in[6];
  float* out = (float*)d_out;

  __half *Qp, *Kp, *Vp, *Op, *Xq, *Xk, *Xv, *Wqh, *Wkh, *Wvh, *Woh;
  cudaGetSymbolAddress((void**)&Qp, g_Qh);
  cudaGetSymbolAddress((void**)&Kp, g_Kh);
  cudaGetSymbolAddress((void**)&Vp, g_Vh);
  cudaGetSymbolAddress((void**)&Op, g_Oh);
  cudaGetSymbolAddress((void**)&Xq, g_Xq);
  cudaGetSymbolAddress((void**)&Xk, g_Xk);
  cudaGetSymbolAddress((void**)&Xv, g_Xv);
  cudaGetSymbolAddress((void**)&Wqh, g_Wq);
  cudaGetSymbolAddress((void**)&Wkh, g_Wk);
  cudaGetSymbolAddress((void**)&Wvh, g_Wv);
  cudaGetSymbolAddress((void**)&Woh, g_Wo);

  cudaFuncSetAttribute(gemm_qkv, cudaFuncAttributeMaxDynamicSharedMemorySize, GEMM_SMEM);
  cudaFuncSetAttribute(gemm_out, cudaFuncAttributeMaxDynamicSharedMemorySize, GEMM_SMEM);
  cudaFuncSetAttribute(attn_f16, cudaFuncAttributeMaxDynamicSharedMemorySize, ATT_SMEM);

  // single-launch convert of inputs + weights
  ConvArgs ca;
  ca.src[0] = query; ca.src[1] = key; ca.src[2] = value;
  ca.src[3] = Wq;    ca.src[4] = Wk;  ca.src[5] = Wv;  ca.src[6] = Wo;
  ca.dst[0] = Xq;    ca.dst[1] = Xk;  ca.dst[2] = Xv;
  ca.dst[3] = Wqh;   ca.dst[4] = Wkh; ca.dst[5] = Wvh; ca.dst[6] = Woh;
  conv_all<<<28672, 256>>>(ca);

  dim3 gq(E_/BN, M_/BM, 3);   // (8, 32, 3) = 768 CTAs
  gemm_qkv<<<gq, 512, GEMM_SMEM>>>(Xq, Xk, Xv, Wqh, Wkh, Wvh, Qp, Kp, Vp);
  attn_f16<<<dim3(S_/128, B_*H_), 256, ATT_SMEM>>>(Qp, Kp, Vp, Op);
  gemm_out<<<dim3(E_/BN, M_/BM), 512, GEMM_SMEM>>>(Op, Woh, out);
}

// round 13
// speedup vs baseline: 1.1469x; 1.1469x over previous
#include <cuda_runtime.h>
#include <cuda_fp16.h>
#include <mma.h>
#include <cstdint>

using namespace nvcuda;

// Problem constants (fixed by the reference)
#define B_ 4
#define S_ 2048
#define E_ 1024
#define H_ 16
#define D_ 64
#define M_ (B_*S_)   // 8192 rows

// Scratch (device globals: allocation-free rule)
__device__ __half g_Qh[M_*E_];   // fp16 rope'd+scaled Q
__device__ __half g_Kh[M_*E_];   // fp16 rope'd K
__device__ __half g_Vh[M_*E_];   // fp16 V
__device__ __half g_Oh[M_*E_];   // attention output
__device__ __half g_Xq[M_*E_];   // fp16 inputs
__device__ __half g_Xk[M_*E_];
__device__ __half g_Xv[M_*E_];
__device__ __half g_Wq[E_*E_];   // fp16 weights
__device__ __half g_Wk[E_*E_];
__device__ __half g_Wv[E_*E_];
__device__ __half g_Wo[E_*E_];
__device__ float  g_Qf[M_*E_];   // fp32 projection outputs (pre-RoPE)
__device__ float  g_Kf[M_*E_];
__device__ float  g_Vf[M_*E_];

#define ROPE_C (13.287712379549449f / 32.0f)   // log2(10000)/32
#define QSCALE 0.18033688011112042f            // (1/8)*log2(e)

// ---------------------------------------------------------------------------
// One-launch fp32->fp16 convert of all 7 input tensors.
// Blocks 0..24575: inputs (3 x 8192). 24576..28671: weights (4 x 1024).
// ---------------------------------------------------------------------------
struct ConvArgs {
  const float* src[7];
  __half* dst[7];
};
__global__ void conv_all(ConvArgs a) {
  int bid = blockIdx.x;
  int z, off;
  if (bid < 24576) { z = bid >> 13;                 off = bid & 8191; }
  else             { z = 3 + ((bid - 24576) >> 10); off = (bid - 24576) & 1023; }
  int i = off * 256 + threadIdx.x;
  float4 v = ((const float4*)a.src[z])[i];
  __half2 h0 = __floats2half2_rn(v.x, v.y);
  __half2 h1 = __floats2half2_rn(v.z, v.w);
  uint2 u; u.x = *(uint32_t*)&h0; u.y = *(uint32_t*)&h1;
  ((uint2*)a.dst[z])[i] = u;
}

// ---------------------------------------------------------------------------
// RoPE (Q,K) + fp16 convert (Q,K,V) from fp32 projection scratch.
// Blocks 0..16383: Q/K rope (B*S*H*32 threads). 16384..24575: V convert.
// ---------------------------------------------------------------------------
__global__ void rope_conv(const float* __restrict__ Qf, const float* __restrict__ Kf,
                          const float* __restrict__ Vf,
                          __half* __restrict__ Qh, __half* __restrict__ Kh,
                          __half* __restrict__ Vh) {
  int bid = blockIdx.x;
  if (bid < 16384) {
    int idx = bid * 256 + threadIdx.x;
    int i = idx & 31;
    int hh = (idx >> 5) & 15;
    int s = (idx >> 9) & 2047;
    int b = idx >> 20;
    float inv = exp2f(-(float)i * ROPE_C);
    float ang = (float)s * inv;
    float sv, cv;
    sincosf(ang, &sv, &cv);
    size_t base = ((size_t)(b*S_ + s))*E_ + hh*64 + i;
    float q1 = Qf[base], q2 = Qf[base+32];
    Qh[base]    = __float2half((q1*cv - q2*sv) * QSCALE);
    Qh[base+32] = __float2half((q2*cv + q1*sv) * QSCALE);
    float k1 = Kf[base], k2 = Kf[base+32];
    Kh[base]    = __float2half(k1*cv - k2*sv);
    Kh[base+32] = __float2half(k2*cv + k1*sv);
  } else {
    int i = (bid - 16384) * 256 + threadIdx.x;
    float4 v = ((const float4*)Vf)[i];
    __half2 h0 = __floats2half2_rn(v.x, v.y);
    __half2 h1 = __floats2half2_rn(v.z, v.w);
    uint2 u; u.x = *(uint32_t*)&h0; u.y = *(uint32_t*)&h1;
    ((uint2*)Vh)[i] = u;
  }
}

// ---------------------------------------------------------------------------
__device__ __forceinline__ uint32_t smem_u32(const void* p) {
  uint32_t a;
  asm("{ .reg .u64 t; cvta.to.shared.u64 t, %1; cvt.u32.u64 %0, t; }" : "=r"(a) : "l"(p));
  return a;
}
__device__ __forceinline__ void cp16(uint32_t dst, const void* src) {
  asm volatile("cp.async.cg.shared.global [%0], [%1], 16;" :: "r"(dst), "l"(src));
}
#define CP_COMMIT() asm volatile("cp.async.commit_group;" ::: "memory")
#define CP_WAIT0()  asm volatile("cp.async.wait_group 0;" ::: "memory")
#define CP_WAIT1()  asm volatile("cp.async.wait_group 1;" ::: "memory")

// ---------------------------------------------------------------------------
// GEMM: block tile 256x128, BK=64, 512 threads (16 warps, 4/SMSP),
// warp tile 32x64, 3-stage cp.async pipeline. Direct fp32 stores (measured
// 69us/GEMM in R10). NT: C[m,n] = sum_k A[m,k]*W[n,k].
// ---------------------------------------------------------------------------
#define BM 256
#define BN 128
#define BK 64
#define LDH 72
#define A_STG (BM*LDH)
#define B_STG (BN*LDH)
#define STG_TOT (A_STG + B_STG)
#define NSTAGE 3
#define GEMM_SMEM (NSTAGE*STG_TOT*2)    // 165888 bytes

__device__ __forceinline__ void gemm_mainloop(
    const __half* __restrict__ A, const __half* __restrict__ W,
    __half* sh, int m0, int n0,
    wmma::fragment<wmma::accumulator, 16, 16, 16, float> (&acc)[2][4]) {
  const int tid = threadIdx.x;
  const int wid = tid >> 5;
  const int wm = wid & 7;
  const int wn = wid >> 3;
  const uint32_t sb = smem_u32(sh);
  const int K = E_;

  auto stage = [&](int kt) {
    const int s = kt % NSTAGE;
    const uint32_t sbase = sb + (uint32_t)(s * STG_TOT) * 2;
    const __half* Ab = A + (size_t)m0 * K + kt * BK;
    const __half* Wb = W + (size_t)n0 * K + kt * BK;
    #pragma unroll
    for (int it = 0; it < 4; it++) {
      int idx = it * 512 + tid;
      int r = idx >> 3, c = (idx & 7) * 8;
      cp16(sbase + (uint32_t)(r*LDH + c) * 2, Ab + (size_t)r * K + c);
    }
    #pragma unroll
    for (int it = 0; it < 2; it++) {
      int idx = it * 512 + tid;
      int r = idx >> 3, c = (idx & 7) * 8;
      cp16(sbase + (uint32_t)(A_STG + r*LDH + c) * 2, Wb + (size_t)r * K + c);
    }
    CP_COMMIT();
  };

  #pragma unroll
  for (int i = 0; i < 2; i++)
    #pragma unroll
    for (int j = 0; j < 4; j++) wmma::fill_fragment(acc[i][j], 0.0f);

  const int ntile = K / BK;
  stage(0); stage(1);
  for (int t = 0; t < ntile; t++) {
    if (t < ntile - 1) { CP_WAIT1(); } else { CP_WAIT0(); }
    __syncthreads();
    if (t + 2 < ntile) stage(t + 2);
    const __half (*As)[LDH] = (const __half(*)[LDH])(sh + (t % NSTAGE)*STG_TOT);
    const __half (*Bs)[LDH] = (const __half(*)[LDH])(sh + (t % NSTAGE)*STG_TOT + A_STG);
    #pragma unroll
    for (int ks = 0; ks < BK; ks += 16) {
      wmma::fragment<wmma::matrix_a, 16, 16, 16, __half, wmma::row_major> af[2];
      wmma::fragment<wmma::matrix_b, 16, 16, 16, __half, wmma::col_major> bf[4];
      #pragma unroll
      for (int i = 0; i < 2; i++)
        wmma::load_matrix_sync(af[i], &As[wm*32 + i*16][ks], LDH);
      #pragma unroll
      for (int j = 0; j < 4; j++)
        wmma::load_matrix_sync(bf[j], &Bs[wn*64 + j*16][ks], LDH);
      #pragma unroll
      for (int i = 0; i < 2; i++)
        #pragma unroll
        for (int j = 0; j < 4; j++)
          wmma::mma_sync(acc[i][j], af[i], bf[j], acc[i][j]);
    }
  }
}

// ---------------------------------------------------------------------------
// Fused QKV projection -> fp32 scratch, direct stores (cheap epilogue).
// mode z: 0=Q, 1=K, 2=V.
// ---------------------------------------------------------------------------
__global__ __launch_bounds__(512)
void gemm_qkv(const __half* __restrict__ Xq, const __half* __restrict__ Xk,
              const __half* __restrict__ Xv,
              const __half* __restrict__ Wq, const __half* __restrict__ Wk,
              const __half* __restrict__ Wv,
              float* __restrict__ Qf, float* __restrict__ Kf,
              float* __restrict__ Vf) {
  extern __shared__ __half sh[];
  const int mode = blockIdx.z;
  const __half* A = (mode == 0) ? Xq : (mode == 1) ? Xk : Xv;
  const __half* W = (mode == 0) ? Wq : (mode == 1) ? Wk : Wv;
  float* C        = (mode == 0) ? Qf : (mode == 1) ? Kf : Vf;
  const int m0 = blockIdx.y * BM, n0 = blockIdx.x * BN;
  const int tid = threadIdx.x;
  const int wid = tid >> 5, wm = wid & 7, wn = wid >> 3;

  wmma::fragment<wmma::accumulator, 16, 16, 16, float> acc[2][4];
  gemm_mainloop(A, W, sh, m0, n0, acc);

  #pragma unroll
  for (int i = 0; i < 2; i++)
    #pragma unroll
    for (int j = 0; j < 4; j++)
      wmma::store_matrix_sync(&C[(size_t)(m0 + wm*32 + i*16) * E_ + n0 + wn*64 + j*16],
                              acc[i][j], E_, wmma::mem_row_major);
}

// ---------------------------------------------------------------------------
// Output projection: fp16 in, fp32 out (identical epilogue; measured 69us).
// ---------------------------------------------------------------------------
__global__ __launch_bounds__(512)
void gemm_out(const __half* __restrict__ A, const __half* __restrict__ W,
              float* __restrict__ C) {
  extern __shared__ __half sh[];
  const int m0 = blockIdx.y * BM, n0 = blockIdx.x * BN;
  const int tid = threadIdx.x;
  const int wid = tid >> 5, wm = wid & 7, wn = wid >> 3;

  wmma::fragment<wmma::accumulator, 16, 16, 16, float> acc[2][4];
  gemm_mainloop(A, W, sh, m0, n0, acc);

  #pragma unroll
  for (int i = 0; i < 2; i++)
    #pragma unroll
    for (int j = 0; j < 4; j++)
      wmma::store_matrix_sync(&C[(size_t)(m0 + wm*32 + i*16) * E_ + n0 + wn*64 + j*16],
                              acc[i][j], E_, wmma::mem_row_major);
}

// ---------------------------------------------------------------------------
// Causal flash attention, 128-row query tiles (best-known config).
// ---------------------------------------------------------------------------
#define LA 72
#define ATT_SMEM (36864 + 18432 + 18432 + 18432 + 18432)   // 110592

__global__ __launch_bounds__(256)
void attn_f16(const __half* __restrict__ Q, const __half* __restrict__ K,
              const __half* __restrict__ V, __half* __restrict__ O) {
  extern __shared__ char smraw[];
  float  (*Ss)[LA]     = (float(*)[LA])(smraw);
  __half (*Qh)[LA]     = (__half(*)[LA])(smraw + 36864);
  __half (*Kh)[64][LA] = (__half(*)[64][LA])(smraw + 55296);
  __half (*Vh)[64][LA] = (__half(*)[64][LA])(smraw + 73728);
  __half (*Ph)[LA]     = (__half(*)[LA])(smraw + 92160);

  const int tid = threadIdx.x;
  const int wid = tid >> 5;
  const int b = blockIdx.y >> 4, h = blockIdx.y & 15;
  const int q0 = blockIdx.x * 128;

  const size_t gbase = (size_t)(b*S_)*E_ + h*64;
  const uint32_t kb0 = smem_u32(&Kh[0][0][0]);
  const uint32_t vb0 = smem_u32(&Vh[0][0][0]);

  auto prefetch = [&](int t) {
    int s = t & 1;
    #pragma unroll
    for (int it = 0; it < 2; it++) {
      int idx = it*256 + tid;
      int r = idx >> 3, c = (idx & 7) * 8;
      const __half* ks = K + gbase + (size_t)(t*64 + r)*E_ + c;
      const __half* vs = V + gbase + (size_t)(t*64 + r)*E_ + c;
      cp16(kb0 + (uint32_t)(s*64*LA + r*LA + c) * 2, ks);
      cp16(vb0 + (uint32_t)(s*64*LA + r*LA + c) * 2, vs);
    }
    CP_COMMIT();
  };

  {
    #pragma unroll
    for (int it = 0; it < 4; it++) {
      int idx = it*256 + tid;
      int r = idx >> 3, c = (idx & 7) * 8;
      *(uint4*)&Qh[r][c] = *(const uint4*)(Q + gbase + (size_t)(q0 + r)*E_ + c);
    }
  }

  const int row = tid >> 1;
  const int c0  = (tid & 1) * 32;

  float o[32];
  #pragma unroll
  for (int j = 0; j < 32; j++) o[j] = 0.f;
  float m_i = -1e30f, l_i = 0.f;

  const int nt = q0/64 + 2;
  prefetch(0);
  for (int t = 0; t < nt; t++) {
    const int k0 = t*64;
    const int s = t & 1;
    CP_WAIT0();
    __syncthreads();
    if (t + 1 < nt) prefetch(t + 1);

    { // S = Q K^T
      wmma::fragment<wmma::accumulator, 16, 16, 16, float> sa[4];
      #pragma unroll
      for (int j = 0; j < 4; j++) wmma::fill_fragment(sa[j], 0.0f);
      #pragma unroll
      for (int ks_ = 0; ks_ < 64; ks_ += 16) {
        wmma::fragment<wmma::matrix_a, 16, 16, 16, __half, wmma::row_major> af;
        wmma::load_matrix_sync(af, &Qh[wid*16][ks_], LA);
        #pragma unroll
        for (int j = 0; j < 4; j++) {
          wmma::fragment<wmma::matrix_b, 16, 16, 16, __half, wmma::col_major> bf;
          wmma::load_matrix_sync(bf, &Kh[s][j*16][ks_], LA);
          wmma::mma_sync(sa[j], af, bf, sa[j]);
        }
      }
      #pragma unroll
      for (int j = 0; j < 4; j++)
        wmma::store_matrix_sync(&Ss[wid*16][j*16], sa[j], LA, wmma::mem_row_major);
    }
    __syncthreads();

    float corr;
    {
      float sv[32];
      #pragma unroll
      for (int j = 0; j < 32; j++) {
        float sc = Ss[row][c0+j];
        sv[j] = (k0 + c0 + j > q0 + row) ? -1e30f : sc;
      }
      float rm = sv[0];
      #pragma unroll
      for (int j = 1; j < 32; j++) rm = fmaxf(rm, sv[j]);
      rm = fmaxf(rm, __shfl_xor_sync(0xffffffffu, rm, 1));
      float mn = fmaxf(m_i, rm);
      corr = exp2f(m_i - mn);
      m_i = mn;
      float rs = 0.f;
      #pragma unroll
      for (int j = 0; j < 32; j += 2) {
        float p0 = exp2f(sv[j]   - mn);
        float p1 = exp2f(sv[j+1] - mn);
        rs += p0 + p1;
        *(half2*)&Ph[row][c0+j] = __floats2half2_rn(p0, p1);
      }
      rs += __shfl_xor_sync(0xffffffffu, rs, 1);
      l_i = l_i*corr + rs;
    }
    __syncthreads();

    { // O_part = P V
      wmma::fragment<wmma::accumulator, 16, 16, 16, float> oa[4];
      #pragma unroll
      for (int j = 0; j < 4; j++) wmma::fill_fragment(oa[j], 0.0f);
      #pragma unroll
      for (int ks_ = 0; ks_ < 64; ks_ += 16) {
        wmma::fragment<wmma::matrix_a, 16, 16, 16, __half, wmma::row_major> af;
        wmma::load_matrix_sync(af, &Ph[wid*16][ks_], LA);
        #pragma unroll
        for (int j = 0; j < 4; j++) {
          wmma::fragment<wmma::matrix_b, 16, 16, 16, __half, wmma::row_major> bf;
          wmma::load_matrix_sync(bf, &Vh[s][ks_][j*16], LA);
          wmma::mma_sync(oa[j], af, bf, oa[j]);
        }
      }
      #pragma unroll
      for (int j = 0; j < 4; j++)
        wmma::store_matrix_sync(&Ss[wid*16][j*16], oa[j], LA, wmma::mem_row_major);
    }
    __syncthreads();

    #pragma unroll
    for (int j = 0; j < 32; j++)
      o[j] = o[j]*corr + Ss[row][c0+j];
  }

  {
    float inv = 1.0f / l_i;
    __half* dst = O + gbase + (size_t)(q0 + row)*E_ + c0;
    uint32_t pk[16];
    #pragma unroll
    for (int j = 0; j < 16; j++) {
      __half2 h2 = __floats2half2_rn(o[2*j]*inv, o[2*j+1]*inv);
      pk[j] = *(uint32_t*)&h2;
    }
    #pragma unroll
    for (int q = 0; q < 4; q++)
      *(uint4*)(dst + q*8) = *(uint4*)&pk[q*4];
  }
}

// ---------------------------------------------------------------------------
extern "C" void kernel_launch(void* const* d_in, const int* in_sizes, int n_in,
                              void* d_out, int out_size) {
  (void)in_sizes; (void)n_in; (void)out_size;
  const float* query = (const float*)d_in[0];
  const float* key   = (const float*)d_in[1];
  const float* value = (const float*)d_in[2];
  const float* Wq    = (const float*)d_in[3];
  const float* Wk    = (const float*)d_in[4];
  const float* Wv    = (const float*)d_in[5];
  const float* Wo    = (const float*)d_in[6];
  float* out = (float*)d_out;

  __half *Qp, *Kp, *Vp, *Op, *Xq, *Xk, *Xv, *Wqh, *Wkh, *Wvh, *Woh;
  float *Qf, *Kf, *Vf;
  cudaGetSymbolAddress((void**)&Qp, g_Qh);
  cudaGetSymbolAddress((void**)&Kp, g_Kh);
  cudaGetSymbolAddress((void**)&Vp, g_Vh);
  cudaGetSymbolAddress((void**)&Op, g_Oh);
  cudaGetSymbolAddress((void**)&Xq, g_Xq);
  cudaGetSymbolAddress((void**)&Xk, g_Xk);
  cudaGetSymbolAddress((void**)&Xv, g_Xv);
  cudaGetSymbolAddress((void**)&Wqh, g_Wq);
  cudaGetSymbolAddress((void**)&Wkh, g_Wk);
  cudaGetSymbolAddress((void**)&Wvh, g_Wv);
  cudaGetSymbolAddress((void**)&Woh, g_Wo);
  cudaGetSymbolAddress((void**)&Qf, g_Qf);
  cudaGetSymbolAddress((void**)&Kf, g_Kf);
  cudaGetSymbolAddress((void**)&Vf, g_Vf);

  cudaFuncSetAttribute(gemm_qkv, cudaFuncAttributeMaxDynamicSharedMemorySize, GEMM_SMEM);
  cudaFuncSetAttribute(gemm_out, cudaFuncAttributeMaxDynamicSharedMemorySize, GEMM_SMEM);
  cudaFuncSetAttribute(attn_f16, cudaFuncAttributeMaxDynamicSharedMemorySize, ATT_SMEM);

  ConvArgs ca;
  ca.src[0] = query; ca.src[1] = key; ca.src[2] = value;
  ca.src[3] = Wq;    ca.src[4] = Wk;  ca.src[5] = Wv;  ca.src[6] = Wo;
  ca.dst[0] = Xq;    ca.dst[1] = Xk;  ca.dst[2] = Xv;
  ca.dst[3] = Wqh;   ca.dst[4] = Wkh; ca.dst[5] = Wvh; ca.dst[6] = Woh;
  conv_all<<<28672, 256>>>(ca);

  dim3 gq(E_/BN, M_/BM, 3);   // (8, 32, 3) = 768 CTAs
  gemm_qkv<<<gq, 512, GEMM_SMEM>>>(Xq, Xk, Xv, Wqh, Wkh, Wvh, Qf, Kf, Vf);
  rope_conv<<<24576, 256>>>(Qf, Kf, Vf, Qp, Kp, Vp);
  attn_f16<<<dim3(S_/128, B_*H_), 256, ATT_SMEM>>>(Qp, Kp, Vp, Op);
  gemm_out<<<dim3(E_/BN, M_/BM), 512, GEMM_SMEM>>>(Op, Woh, out);
}

// round 15
// speedup vs baseline: 1.4142x; 1.2331x over previous
#include <cuda_runtime.h>
#include <cuda_fp16.h>
#include <mma.h>
#include <cstdint>

using namespace nvcuda;

// Problem constants (fixed by the reference)
#define B_ 4
#define S_ 2048
#define E_ 1024
#define H_ 16
#define D_ 64
#define M_ (B_*S_)   // 8192 rows

// Scratch (device globals: allocation-free rule)
__device__ __half g_Qh[M_*E_];   // fp16 rope'd+scaled Q
__device__ __half g_Kh[M_*E_];   // fp16 rope'd K
__device__ __half g_Vh[M_*E_];   // fp16 V
__device__ __half g_Oh[M_*E_];   // attention output
__device__ __half g_Xq[M_*E_];   // fp16 inputs
__device__ __half g_Xk[M_*E_];
__device__ __half g_Xv[M_*E_];
__device__ __half g_Wq[E_*E_];   // fp16 weights
__device__ __half g_Wk[E_*E_];
__device__ __half g_Wv[E_*E_];
__device__ __half g_Wo[E_*E_];
__device__ float  g_Qf[M_*E_];   // fp32 projection outputs (pre-RoPE)
__device__ float  g_Kf[M_*E_];
__device__ float  g_Vf[M_*E_];

#define ROPE_C (13.287712379549449f / 32.0f)   // log2(10000)/32
#define QSCALE 0.18033688011112042f            // (1/8)*log2(e)

// ---------------------------------------------------------------------------
// One-launch fp32->fp16 convert of all 7 input tensors.
// ---------------------------------------------------------------------------
struct ConvArgs {
  const float* src[7];
  __half* dst[7];
};
__global__ void conv_all(ConvArgs a) {
  int bid = blockIdx.x;
  int z, off;
  if (bid < 24576) { z = bid >> 13;                 off = bid & 8191; }
  else             { z = 3 + ((bid - 24576) >> 10); off = (bid - 24576) & 1023; }
  int i = off * 256 + threadIdx.x;
  float4 v = ((const float4*)a.src[z])[i];
  __half2 h0 = __floats2half2_rn(v.x, v.y);
  __half2 h1 = __floats2half2_rn(v.z, v.w);
  uint2 u; u.x = *(uint32_t*)&h0; u.y = *(uint32_t*)&h1;
  ((uint2*)a.dst[z])[i] = u;
}

// ---------------------------------------------------------------------------
// RoPE (Q,K) + fp16 convert (Q,K,V) from fp32 projection scratch.
// ---------------------------------------------------------------------------
__global__ void rope_conv(const float* __restrict__ Qf, const float* __restrict__ Kf,
                          const float* __restrict__ Vf,
                          __half* __restrict__ Qh, __half* __restrict__ Kh,
                          __half* __restrict__ Vh) {
  int bid = blockIdx.x;
  if (bid < 16384) {
    int idx = bid * 256 + threadIdx.x;
    int i = idx & 31;
    int hh = (idx >> 5) & 15;
    int s = (idx >> 9) & 2047;
    int b = idx >> 20;
    float inv = exp2f(-(float)i * ROPE_C);
    float ang = (float)s * inv;
    float sv, cv;
    sincosf(ang, &sv, &cv);
    size_t base = ((size_t)(b*S_ + s))*E_ + hh*64 + i;
    float q1 = Qf[base], q2 = Qf[base+32];
    Qh[base]    = __float2half((q1*cv - q2*sv) * QSCALE);
    Qh[base+32] = __float2half((q2*cv + q1*sv) * QSCALE);
    float k1 = Kf[base], k2 = Kf[base+32];
    Kh[base]    = __float2half(k1*cv - k2*sv);
    Kh[base+32] = __float2half(k2*cv + k1*sv);
  } else {
    int i = (bid - 16384) * 256 + threadIdx.x;
    float4 v = ((const float4*)Vf)[i];
    __half2 h0 = __floats2half2_rn(v.x, v.y);
    __half2 h1 = __floats2half2_rn(v.z, v.w);
    uint2 u; u.x = *(uint32_t*)&h0; u.y = *(uint32_t*)&h1;
    ((uint2*)Vh)[i] = u;
  }
}

// ---------------------------------------------------------------------------
__device__ __forceinline__ uint32_t smem_u32(const void* p) {
  uint32_t a;
  asm("{ .reg .u64 t; cvta.to.shared.u64 t, %1; cvt.u32.u64 %0, t; }" : "=r"(a) : "l"(p));
  return a;
}
__device__ __forceinline__ void cp16(uint32_t dst, const void* src) {
  asm volatile("cp.async.cg.shared.global [%0], [%1], 16;" :: "r"(dst), "l"(src));
}
#define CP_COMMIT() asm volatile("cp.async.commit_group;" ::: "memory")
#define CP_WAIT0()  asm volatile("cp.async.wait_group 0;" ::: "memory")
#define CP_WAIT1()  asm volatile("cp.async.wait_group 1;" ::: "memory")

// mma / ldmatrix primitives
__device__ __forceinline__ void mma16816(float* c, const uint32_t* a, const uint32_t* b) {
  asm volatile("mma.sync.aligned.m16n8k16.row.col.f32.f16.f16.f32 "
    "{%0,%1,%2,%3}, {%4,%5,%6,%7}, {%8,%9}, {%0,%1,%2,%3};"
    : "+f"(c[0]), "+f"(c[1]), "+f"(c[2]), "+f"(c[3])
    : "r"(a[0]), "r"(a[1]), "r"(a[2]), "r"(a[3]), "r"(b[0]), "r"(b[1]));
}
__device__ __forceinline__ void ldsm4(uint32_t* r, uint32_t a) {
  asm volatile("ldmatrix.sync.aligned.m8n8.x4.shared.b16 {%0,%1,%2,%3}, [%4];"
    : "=r"(r[0]), "=r"(r[1]), "=r"(r[2]), "=r"(r[3]) : "r"(a));
}
__device__ __forceinline__ void ldsm4t(uint32_t* r, uint32_t a) {
  asm volatile("ldmatrix.sync.aligned.m8n8.x4.trans.shared.b16 {%0,%1,%2,%3}, [%4];"
    : "=r"(r[0]), "=r"(r[1]), "=r"(r[2]), "=r"(r[3]) : "r"(a));
}
__device__ __forceinline__ uint32_t f2h2(float a, float b) {
  __half2 h = __floats2half2_rn(a, b);
  return *(uint32_t*)&h;
}

// ---------------------------------------------------------------------------
// GEMM: block tile 256x128, BK=64, 512 threads, 3-stage cp.async pipeline.
// (Unchanged from R12; gemm_out measured at 69us.)
// ---------------------------------------------------------------------------
#define BM 256
#define BN 128
#define BK 64
#define LDH 72
#define A_STG (BM*LDH)
#define B_STG (BN*LDH)
#define STG_TOT (A_STG + B_STG)
#define NSTAGE 3
#define GEMM_SMEM (NSTAGE*STG_TOT*2)    // 165888 bytes

__device__ __forceinline__ void gemm_mainloop(
    const __half* __restrict__ A, const __half* __restrict__ W,
    __half* sh, int m0, int n0,
    wmma::fragment<wmma::accumulator, 16, 16, 16, float> (&acc)[2][4]) {
  const int tid = threadIdx.x;
  const int wid = tid >> 5;
  const int wm = wid & 7;
  const int wn = wid >> 3;
  const uint32_t sb = smem_u32(sh);
  const int K = E_;

  auto stage = [&](int kt) {
    const int s = kt % NSTAGE;
    const uint32_t sbase = sb + (uint32_t)(s * STG_TOT) * 2;
    const __half* Ab = A + (size_t)m0 * K + kt * BK;
    const __half* Wb = W + (size_t)n0 * K + kt * BK;
    #pragma unroll
    for (int it = 0; it < 4; it++) {
      int idx = it * 512 + tid;
      int r = idx >> 3, c = (idx & 7) * 8;
      cp16(sbase + (uint32_t)(r*LDH + c) * 2, Ab + (size_t)r * K + c);
    }
    #pragma unroll
    for (int it = 0; it < 2; it++) {
      int idx = it * 512 + tid;
      int r = idx >> 3, c = (idx & 7) * 8;
      cp16(sbase + (uint32_t)(A_STG + r*LDH + c) * 2, Wb + (size_t)r * K + c);
    }
    CP_COMMIT();
  };

  #pragma unroll
  for (int i = 0; i < 2; i++)
    #pragma unroll
    for (int j = 0; j < 4; j++) wmma::fill_fragment(acc[i][j], 0.0f);

  const int ntile = K / BK;
  stage(0); stage(1);
  for (int t = 0; t < ntile; t++) {
    if (t < ntile - 1) { CP_WAIT1(); } else { CP_WAIT0(); }
    __syncthreads();
    if (t + 2 < ntile) stage(t + 2);
    const __half (*As)[LDH] = (const __half(*)[LDH])(sh + (t % NSTAGE)*STG_TOT);
    const __half (*Bs)[LDH] = (const __half(*)[LDH])(sh + (t % NSTAGE)*STG_TOT + A_STG);
    #pragma unroll
    for (int ks = 0; ks < BK; ks += 16) {
      wmma::fragment<wmma::matrix_a, 16, 16, 16, __half, wmma::row_major> af[2];
      wmma::fragment<wmma::matrix_b, 16, 16, 16, __half, wmma::col_major> bf[4];
      #pragma unroll
      for (int i = 0; i < 2; i++)
        wmma::load_matrix_sync(af[i], &As[wm*32 + i*16][ks], LDH);
      #pragma unroll
      for (int j = 0; j < 4; j++)
        wmma::load_matrix_sync(bf[j], &Bs[wn*64 + j*16][ks], LDH);
      #pragma unroll
      for (int i = 0; i < 2; i++)
        #pragma unroll
        for (int j = 0; j < 4; j++)
          wmma::mma_sync(acc[i][j], af[i], bf[j], acc[i][j]);
    }
  }
}

__global__ __launch_bounds__(512)
void gemm_qkv(const __half* __restrict__ Xq, const __half* __restrict__ Xk,
              const __half* __restrict__ Xv,
              const __half* __restrict__ Wq, const __half* __restrict__ Wk,
              const __half* __restrict__ Wv,
              float* __restrict__ Qf, float* __restrict__ Kf,
              float* __restrict__ Vf) {
  extern __shared__ __half sh[];
  const int mode = blockIdx.z;
  const __half* A = (mode == 0) ? Xq : (mode == 1) ? Xk : Xv;
  const __half* W = (mode == 0) ? Wq : (mode == 1) ? Wk : Wv;
  float* C        = (mode == 0) ? Qf : (mode == 1) ? Kf : Vf;
  const int m0 = blockIdx.y * BM, n0 = blockIdx.x * BN;
  const int tid = threadIdx.x;
  const int wid = tid >> 5, wm = wid & 7, wn = wid >> 3;

  wmma::fragment<wmma::accumulator, 16, 16, 16, float> acc[2][4];
  gemm_mainloop(A, W, sh, m0, n0, acc);

  #pragma unroll
  for (int i = 0; i < 2; i++)
    #pragma unroll
    for (int j = 0; j < 4; j++)
      wmma::store_matrix_sync(&C[(size_t)(m0 + wm*32 + i*16) * E_ + n0 + wn*64 + j*16],
                              acc[i][j], E_, wmma::mem_row_major);
}

__global__ __launch_bounds__(512)
void gemm_out(const __half* __restrict__ A, const __half* __restrict__ W,
              float* __restrict__ C) {
  extern __shared__ __half sh[];
  const int m0 = blockIdx.y * BM, n0 = blockIdx.x * BN;
  const int tid = threadIdx.x;
  const int wid = tid >> 5, wm = wid & 7, wn = wid >> 3;

  wmma::fragment<wmma::accumulator, 16, 16, 16, float> acc[2][4];
  gemm_mainloop(A, W, sh, m0, n0, acc);

  #pragma unroll
  for (int i = 0; i < 2; i++)
    #pragma unroll
    for (int j = 0; j < 4; j++)
      wmma::store_matrix_sync(&C[(size_t)(m0 + wm*32 + i*16) * E_ + n0 + wn*64 + j*16],
                              acc[i][j], E_, wmma::mem_row_major);
}

// ---------------------------------------------------------------------------
// Register-resident causal flash attention (raw mma.sync m16n8k16).
// CTA: 128 query rows x (b,h); 256 threads / 8 warps; warp w owns rows w*16..+15.
// Q in A-fragments (regs, loaded once); S in accumulators; softmax in regs
// (quad shuffles); P repacked fp16 in regs -> A-operand of PV; V via
// ldmatrix.x4.trans. Smem: Q[128x72] + 2x(K,V)[64x72] halves = 55296B.
// ---------------------------------------------------------------------------
#define QH_OFF 0
#define KH_OFF (128*LDH)
#define VH_OFF (256*LDH)
#define ATTR_SMEM (384*LDH*2)   // 55296 bytes

__global__ __launch_bounds__(256, 2)
void attn_reg(const __half* __restrict__ Q, const __half* __restrict__ K,
              const __half* __restrict__ V, __half* __restrict__ O) {
  extern __shared__ __half sm[];
  const uint32_t sb = smem_u32(sm);
  const int tid = threadIdx.x;
  const int wid = tid >> 5, lane = tid & 31;
  const int g = lane >> 2, qd = lane & 3;
  const int b = blockIdx.y >> 4, h = blockIdx.y & 15;
  const int q0 = ((int)gridDim.x - 1 - (int)blockIdx.x) * 128;   // heavy CTAs first
  const size_t gb = (size_t)(b*S_)*E_ + h*64;

  // lane-derived ldmatrix offsets (in halves)
  const uint32_t aoff = (uint32_t)((lane & 15)*LDH + (lane >> 4)*8);
  const uint32_t koff = (uint32_t)((lane & 7)*LDH + ((lane >> 3) & 1)*8 + ((lane >> 4) & 1)*16);
  const uint32_t voff = (uint32_t)(((lane & 7) + ((lane >> 3) & 1)*8)*LDH + ((lane >> 4) & 1)*8);

  // stage Q (group 0)
  #pragma unroll
  for (int it = 0; it < 4; it++) {
    int idx = it*256 + tid;
    int r = idx >> 3, c = (idx & 7)*8;
    cp16(sb + (uint32_t)(QH_OFF + r*LDH + c)*2, Q + gb + (size_t)(q0 + r)*E_ + c);
  }
  CP_COMMIT();

  auto prefetch = [&](int t) {
    int s = t & 1;
    #pragma unroll
    for (int it = 0; it < 2; it++) {
      int idx = it*256 + tid;
      int r = idx >> 3, c = (idx & 7)*8;
      cp16(sb + (uint32_t)(KH_OFF + s*64*LDH + r*LDH + c)*2, K + gb + (size_t)(t*64 + r)*E_ + c);
      cp16(sb + (uint32_t)(VH_OFF + s*64*LDH + r*LDH + c)*2, V + gb + (size_t)(t*64 + r)*E_ + c);
    }
    CP_COMMIT();
  };
  prefetch(0);

  CP_WAIT1();                 // Q landed
  __syncthreads();

  // Q fragments: 4 k-steps x 4 regs, loaded once
  uint32_t qa[4][4];
  #pragma unroll
  for (int ks = 0; ks < 4; ks++)
    ldsm4(qa[ks], sb + (uint32_t)(QH_OFF + wid*16*LDH + ks*16 + aoff)*2);

  float oacc[8][4];
  #pragma unroll
  for (int d = 0; d < 8; d++)
    #pragma unroll
    for (int i = 0; i < 4; i++) oacc[d][i] = 0.f;
  float m0 = -1e30f, m1 = -1e30f, l0 = 0.f, l1 = 0.f;

  const int wrow = q0 + wid*16;
  const int nt = q0/64 + 2;
  for (int t = 0; t < nt; t++) {
    const int k0 = t*64, s = t & 1;
    CP_WAIT0();
    __syncthreads();            // tile t ready; all warps past tile t-1 reads
    if (t + 1 < nt) prefetch(t + 1);

    if (k0 <= wrow + 15) {      // warp-uniform: skip fully-masked tiles
      // ---- S = Q K^T ----
      float sacc[8][4];
      #pragma unroll
      for (int j = 0; j < 8; j++)
        #pragma unroll
        for (int i = 0; i < 4; i++) sacc[j][i] = 0.f;
      const uint32_t kbase = sb + (uint32_t)(KH_OFF + s*64*LDH)*2 + koff*2;
      #pragma unroll
      for (int j = 0; j < 8; j++) {
        uint32_t kb[4];
        ldsm4(kb, kbase + (uint32_t)(j*8*LDH)*2);         // k-dims 0..31
        mma16816(sacc[j], qa[0], kb);
        mma16816(sacc[j], qa[1], kb+2);
        ldsm4(kb, kbase + (uint32_t)(j*8*LDH + 32)*2);    // k-dims 32..63
        mma16816(sacc[j], qa[2], kb);
        mma16816(sacc[j], qa[3], kb+2);
      }
      const int gr0 = wrow + g, gr1 = gr0 + 8;
      if (k0 + 63 > wrow) {     // causal mask (border tiles only)
        #pragma unroll
        for (int j = 0; j < 8; j++) {
          int kc = k0 + j*8 + 2*qd;
          if (kc     > gr0) sacc[j][0] = -1e30f;
          if (kc + 1 > gr0) sacc[j][1] = -1e30f;
          if (kc     > gr1) sacc[j][2] = -1e30f;
          if (kc + 1 > gr1) sacc[j][3] = -1e30f;
        }
      }
      // ---- online softmax in registers (exp2 domain) ----
      float mx0 = -1e30f, mx1 = -1e30f;
      #pragma unroll
      for (int j = 0; j < 8; j++) {
        mx0 = fmaxf(mx0, fmaxf(sacc[j][0], sacc[j][1]));
        mx1 = fmaxf(mx1, fmaxf(sacc[j][2], sacc[j][3]));
      }
      mx0 = fmaxf(mx0, __shfl_xor_sync(0xffffffffu, mx0, 1));
      mx0 = fmaxf(mx0, __shfl_xor_sync(0xffffffffu, mx0, 2));
      mx1 = fmaxf(mx1, __shfl_xor_sync(0xffffffffu, mx1, 1));
      mx1 = fmaxf(mx1, __shfl_xor_sync(0xffffffffu, mx1, 2));
      float mn0 = fmaxf(m0, mx0), mn1 = fmaxf(m1, mx1);
      float cr0 = exp2f(m0 - mn0), cr1 = exp2f(m1 - mn1);
      m0 = mn0; m1 = mn1;
      float s0 = 0.f, s1 = 0.f;
      #pragma unroll
      for (int j = 0; j < 8; j++) {
        sacc[j][0] = exp2f(sacc[j][0] - mn0);
        sacc[j][1] = exp2f(sacc[j][1] - mn0);
        sacc[j][2] = exp2f(sacc[j][2] - mn1);
        sacc[j][3] = exp2f(sacc[j][3] - mn1);
        s0 += sacc[j][0] + sacc[j][1];
        s1 += sacc[j][2] + sacc[j][3];
      }
      s0 += __shfl_xor_sync(0xffffffffu, s0, 1);
      s0 += __shfl_xor_sync(0xffffffffu, s0, 2);
      s1 += __shfl_xor_sync(0xffffffffu, s1, 1);
      s1 += __shfl_xor_sync(0xffffffffu, s1, 2);
      l0 = l0*cr0 + s0;
      l1 = l1*cr1 + s1;
      #pragma unroll
      for (int d = 0; d < 8; d++) {
        oacc[d][0] *= cr0; oacc[d][1] *= cr0;
        oacc[d][2] *= cr1; oacc[d][3] *= cr1;
      }
      // ---- O += P V ----
      const uint32_t vbase = sb + (uint32_t)(VH_OFF + s*64*LDH)*2 + voff*2;
      #pragma unroll
      for (int kk = 0; kk < 4; kk++) {
        uint32_t pa[4];
        pa[0] = f2h2(sacc[2*kk][0],   sacc[2*kk][1]);
        pa[1] = f2h2(sacc[2*kk][2],   sacc[2*kk][3]);
        pa[2] = f2h2(sacc[2*kk+1][0], sacc[2*kk+1][1]);
        pa[3] = f2h2(sacc[2*kk+1][2], sacc[2*kk+1][3]);
        #pragma unroll
        for (int dp = 0; dp < 4; dp++) {
          uint32_t vb[4];
          ldsm4t(vb, vbase + (uint32_t)(kk*16*LDH + dp*16)*2);
          mma16816(oacc[2*dp],   pa, vb);
          mma16816(oacc[2*dp+1], pa, vb+2);
        }
      }
    }
  }

  // epilogue: divide by l, store fp16
  {
    const int gr0 = wrow + g;
    float i0 = 1.f / l0, i1 = 1.f / l1;
    __half* r0p = O + gb + (size_t)gr0*E_ + 2*qd;
    __half* r1p = O + gb + (size_t)(gr0+8)*E_ + 2*qd;
    #pragma unroll
    for (int d = 0; d < 8; d++) {
      *(uint32_t*)(r0p + d*8) = f2h2(oacc[d][0]*i0, oacc[d][1]*i0);
      *(uint32_t*)(r1p + d*8) = f2h2(oacc[d][2]*i1, oacc[d][3]*i1);
    }
  }
}

// ---------------------------------------------------------------------------
extern "C" void kernel_launch(void* const* d_in, const int* in_sizes, int n_in,
                              void* d_out, int out_size) {
  (void)in_sizes; (void)n_in; (void)out_size;
  const float* query = (const float*)d_in[0];
  const float* key   = (const float*)d_in[1];
  const float* value = (const float*)d_in[2];
  const float* Wq    = (const float*)d_in[3];
  const float* Wk    = (const float*)d_in[4];
  const float* Wv    = (const float*)d_in[5];
  const float* Wo    = (const float*)d_in[6];
  float* out = (float*)d_out;

  __half *Qp, *Kp, *Vp, *Op, *Xq, *Xk, *Xv, *Wqh, *Wkh, *Wvh, *Woh;
  float *Qf, *Kf, *Vf;
  cudaGetSymbolAddress((void**)&Qp, g_Qh);
  cudaGetSymbolAddress((void**)&Kp, g_Kh);
  cudaGetSymbolAddress((void**)&Vp, g_Vh);
  cudaGetSymbolAddress((void**)&Op, g_Oh);
  cudaGetSymbolAddress((void**)&Xq, g_Xq);
  cudaGetSymbolAddress((void**)&Xk, g_Xk);
  cudaGetSymbolAddress((void**)&Xv, g_Xv);
  cudaGetSymbolAddress((void**)&Wqh, g_Wq);
  cudaGetSymbolAddress((void**)&Wkh, g_Wk);
  cudaGetSymbolAddress((void**)&Wvh, g_Wv);
  cudaGetSymbolAddress((void**)&Woh, g_Wo);
  cudaGetSymbolAddress((void**)&Qf, g_Qf);
  cudaGetSymbolAddress((void**)&Kf, g_Kf);
  cudaGetSymbolAddress((void**)&Vf, g_Vf);

  cudaFuncSetAttribute(gemm_qkv, cudaFuncAttributeMaxDynamicSharedMemorySize, GEMM_SMEM);
  cudaFuncSetAttribute(gemm_out, cudaFuncAttributeMaxDynamicSharedMemorySize, GEMM_SMEM);
  cudaFuncSetAttribute(attn_reg, cudaFuncAttributeMaxDynamicSharedMemorySize, ATTR_SMEM);

  ConvArgs ca;
  ca.src[0] = query; ca.src[1] = key; ca.src[2] = value;
  ca.src[3] = Wq;    ca.src[4] = Wk;  ca.src[5] = Wv;  ca.src[6] = Wo;
  ca.dst[0] = Xq;    ca.dst[1] = Xk;  ca.dst[2] = Xv;
  ca.dst[3] = Wqh;   ca.dst[4] = Wkh; ca.dst[5] = Wvh; ca.dst[6] = Woh;
  conv_all<<<28672, 256>>>(ca);

  dim3 gq(E_/BN, M_/BM, 3);   // 768 CTAs
  gemm_qkv<<<gq, 512, GEMM_SMEM>>>(Xq, Xk, Xv, Wqh, Wkh, Wvh, Qf, Kf, Vf);
  rope_conv<<<24576, 256>>>(Qf, Kf, Vf, Qp, Kp, Vp);
  attn_reg<<<dim3(S_/128, B_*H_), 256, ATTR_SMEM>>>(Qp, Kp, Vp, Op);
  gemm_out<<<dim3(E_/BN, M_/BM), 512, GEMM_SMEM>>>(Op, Woh, out);
}